// round 4
// baseline (speedup 1.0000x reference)
#include <cuda_runtime.h>

#define FFT_M    4096   // complex FFT size (= d/2)
#define NREAL    8192   // sketch / output dim d
#define NTHREADS 512
#define IMG_DIM  2048
#define TXT_DIM  768

// Padded shared-memory indexing: one extra float2 every 32 float2 (256B)
// kills the 8/16-way bank conflicts of the strided Stockham writes.
#define PIDX(i)  ((i) + ((i) >> 5))            // float2 index -> padded float2 index
#define RIDX(i)  ((i) + (((i) >> 6) << 1))     // float  index -> padded float  index
#define PADDED   (FFT_M + (FFT_M >> 5))        // 4224 float2 per buffer

__device__ __forceinline__ float2 cadd(float2 a, float2 b){ return make_float2(a.x+b.x, a.y+b.y); }
__device__ __forceinline__ float2 csub(float2 a, float2 b){ return make_float2(a.x-b.x, a.y-b.y); }
__device__ __forceinline__ float2 cmul(float2 a, float2 b){
    return make_float2(fmaf(a.x, b.x, -a.y*b.y), fmaf(a.x, b.y, a.y*b.x));
}

// Radix-8 Stockham autosort FFT, size 4096, shared memory, padded layout.
// DIR = -1 forward, +1 inverse (unnormalized). 4 stages (even) => result back in x.
// 512 threads: exactly one radix-8 butterfly per thread per stage.
// Ends with __syncthreads().
template<int DIR>
__device__ __forceinline__ void fft4096_r8(float2* __restrict__ x, float2* __restrict__ tmp, int tid) {
    const float c8 = 0.70710678118654752f;
    float2* in  = x;
    float2* out = tmp;
    #pragma unroll
    for (int stage = 0; stage < 4; stage++) {
        const int Ns   = 1 << (3 * stage);          // 1, 8, 64, 512
        const int m    = tid & (Ns - 1);
        const int base = ((tid - m) << 3) + m;

        float2 v0 = in[PIDX(tid)];
        float2 v1 = in[PIDX(tid +  512)];
        float2 v2 = in[PIDX(tid + 1024)];
        float2 v3 = in[PIDX(tid + 1536)];
        float2 v4 = in[PIDX(tid + 2048)];
        float2 v5 = in[PIDX(tid + 2560)];
        float2 v6 = in[PIDX(tid + 3072)];
        float2 v7 = in[PIDX(tid + 3584)];

        // twiddles W_{8Ns}^{r*m}, r=1..7, built as a shallow product tree
        {
            const float ang = (float)DIR * 6.2831853071795864f * (float)m / (8.0f * (float)Ns);
            float s, c; __sincosf(ang, &s, &c);
            float2 w1 = make_float2(c, s);
            float2 w2 = cmul(w1, w1);
            float2 w3 = cmul(w2, w1);
            float2 w4 = cmul(w2, w2);
            float2 w5 = cmul(w3, w2);
            float2 w6 = cmul(w3, w3);
            float2 w7 = cmul(w4, w3);
            v1 = cmul(v1, w1);
            v2 = cmul(v2, w2);
            v3 = cmul(v3, w3);
            v4 = cmul(v4, w4);
            v5 = cmul(v5, w5);
            v6 = cmul(v6, w6);
            v7 = cmul(v7, w7);
        }

        // 8-point FFT: even/odd 4-point FFTs + combine with constant W8^k
        float2 e0, e1, e2, e3, o0, o1, o2, o3;
        {
            float2 t0 = cadd(v0, v4), t1 = csub(v0, v4);
            float2 t2 = cadd(v2, v6), t3 = csub(v2, v6);
            float2 jt3 = (DIR < 0) ? make_float2(t3.y, -t3.x) : make_float2(-t3.y, t3.x);
            e0 = cadd(t0, t2); e2 = csub(t0, t2);
            e1 = cadd(t1, jt3); e3 = csub(t1, jt3);
        }
        {
            float2 t0 = cadd(v1, v5), t1 = csub(v1, v5);
            float2 t2 = cadd(v3, v7), t3 = csub(v3, v7);
            float2 jt3 = (DIR < 0) ? make_float2(t3.y, -t3.x) : make_float2(-t3.y, t3.x);
            o0 = cadd(t0, t2); o2 = csub(t0, t2);
            o1 = cadd(t1, jt3); o3 = csub(t1, jt3);
        }
        // u_k = W8^k * o_k (constants)
        float2 u1 = (DIR < 0) ? make_float2(c8*(o1.x + o1.y), c8*(o1.y - o1.x))
                              : make_float2(c8*(o1.x - o1.y), c8*(o1.x + o1.y));
        float2 u2 = (DIR < 0) ? make_float2(o2.y, -o2.x)
                              : make_float2(-o2.y, o2.x);
        float2 u3 = (DIR < 0) ? make_float2(c8*(o3.y - o3.x), -c8*(o3.x + o3.y))
                              : make_float2(-c8*(o3.x + o3.y), c8*(o3.x - o3.y));

        out[PIDX(base         )] = cadd(e0, o0);
        out[PIDX(base + 4 * Ns)] = csub(e0, o0);
        out[PIDX(base + 1 * Ns)] = cadd(e1, u1);
        out[PIDX(base + 5 * Ns)] = csub(e1, u1);
        out[PIDX(base + 2 * Ns)] = cadd(e2, u2);
        out[PIDX(base + 6 * Ns)] = csub(e2, u2);
        out[PIDX(base + 3 * Ns)] = cadd(e3, u3);
        out[PIDX(base + 7 * Ns)] = csub(e3, u3);

        __syncthreads();
        float2* sw = in; in = out; out = sw;
    }
}

__global__ void __launch_bounds__(NTHREADS)
bilinear_fusion_kernel(
    const float* __restrict__ img,  const float* __restrict__ txt,
    const int*   __restrict__ h1,   const int*   __restrict__ h2,
    const float* __restrict__ s1,   const float* __restrict__ s2,
    const float* __restrict__ gamma,const float* __restrict__ beta,
    float* __restrict__ out)
{
    extern __shared__ float2 sm[];
    float2* A = sm;               // sketch1 -> Z1
    float2* B = sm +   PADDED;    // FFT scratch -> ZY -> y
    float2* C = sm + 2*PADDED;    // sketch2 -> Z2
    __shared__ float rs[16], rq[16];

    const int b   = blockIdx.x;
    const int tid = threadIdx.x;

    // ---- count sketches (scatter-add into smem) ----
    float* rA = (float*)A;
    float* rC = (float*)C;
    for (int i = tid; i < 2 * PADDED; i += NTHREADS) { rA[i] = 0.0f; rC[i] = 0.0f; }
    __syncthreads();

    const float* irow = img + (size_t)b * IMG_DIM;
    for (int i = tid; i < IMG_DIM; i += NTHREADS)
        atomicAdd(&rA[RIDX(h1[i])], irow[i] * s1[i]);
    const float* trow = txt + (size_t)b * TXT_DIM;
    for (int i = tid; i < TXT_DIM; i += NTHREADS)
        atomicAdd(&rC[RIDX(h2[i])], trow[i] * s2[i]);
    __syncthreads();

    // ---- forward FFTs of the packed real signals ----
    fft4096_r8<-1>(A, B, tid);   // Z1 in A
    fft4096_r8<-1>(C, B, tid);   // Z2 in C

    // ---- unpack rFFTs, multiply spectra, repack for inverse ----
    const float scale = 1.0f / (float)FFT_M;
    for (int k = tid; k <= FFT_M/2; k += NTHREADS) {
        int mk = (FFT_M - k) & (FFT_M - 1);
        float2 z1k = A[PIDX(k)],  z1m = A[PIDX(mk)];
        float2 z2k = C[PIDX(k)],  z2m = C[PIDX(mk)];
        float sa, ca;
        __sincosf(-6.2831853071795864f * (float)k / (float)NREAL, &sa, &ca);
        float2 w = make_float2(ca, sa);            // W_N^k

        float2 E1  = make_float2(0.5f*(z1k.x + z1m.x), 0.5f*(z1k.y - z1m.y));
        float2 O1t = make_float2(0.5f*(z1k.x - z1m.x), 0.5f*(z1k.y + z1m.y));
        float2 O1  = make_float2(O1t.y, -O1t.x);   // -i * O1t
        float2 WO1 = cmul(w, O1);
        float2 P1  = cadd(E1, WO1);
        float2 Q1  = csub(E1, WO1);

        float2 E2  = make_float2(0.5f*(z2k.x + z2m.x), 0.5f*(z2k.y - z2m.y));
        float2 O2t = make_float2(0.5f*(z2k.x - z2m.x), 0.5f*(z2k.y + z2m.y));
        float2 O2  = make_float2(O2t.y, -O2t.x);
        float2 WO2 = cmul(w, O2);
        float2 P2  = cadd(E2, WO2);
        float2 Q2  = csub(E2, WO2);

        float2 Yk  = cmul(P1, P2);
        float2 Ymc = cmul(Q1, Q2);                 // conj(Y[M-k])
        float2 G   = make_float2(0.5f*(Yk.x + Ymc.x), 0.5f*(Yk.y + Ymc.y));
        float2 Hm  = make_float2(0.5f*(Yk.x - Ymc.x), 0.5f*(Yk.y - Ymc.y));
        float2 H   = cmul(make_float2(w.x, -w.y), Hm);

        B[PIDX(k)] = make_float2(scale*(G.x - H.y), scale*(G.y + H.x));
        if (k != 0 && k != FFT_M/2) {
            B[PIDX(mk)] = make_float2(scale*(G.x + H.y), scale*(H.x - G.y));
        }
    }
    __syncthreads();

    // ---- inverse FFT: y[2n] = Re, y[2n+1] = Im ----
    fft4096_r8<1>(B, A, tid);

    // ---- LayerNorm over the 8192 reals ----
    float sum = 0.0f, sq = 0.0f;
    for (int n = tid; n < FFT_M; n += NTHREADS) {
        float2 v = B[PIDX(n)];
        sum += v.x + v.y;
        sq = fmaf(v.x, v.x, sq);
        sq = fmaf(v.y, v.y, sq);
    }
    #pragma unroll
    for (int o = 16; o; o >>= 1) {
        sum += __shfl_down_sync(0xffffffffu, sum, o);
        sq  += __shfl_down_sync(0xffffffffu, sq,  o);
    }
    const int wid = tid >> 5, lid = tid & 31;
    if (lid == 0) { rs[wid] = sum; rq[wid] = sq; }
    __syncthreads();
    if (wid == 0) {
        sum = (lid < 16) ? rs[lid] : 0.0f;
        sq  = (lid < 16) ? rq[lid] : 0.0f;
        #pragma unroll
        for (int o = 8; o; o >>= 1) {
            sum += __shfl_down_sync(0xffffffffu, sum, o);
            sq  += __shfl_down_sync(0xffffffffu, sq,  o);
        }
        if (lid == 0) { rs[0] = sum; rq[0] = sq; }
    }
    __syncthreads();
    const float mean = rs[0] * (1.0f / (float)NREAL);
    const float var  = rq[0] * (1.0f / (float)NREAL) - mean * mean;
    const float inv  = rsqrtf(var + 1e-5f);

    float2* orow = (float2*)(out + (size_t)b * NREAL);
    const float2* g2 = (const float2*)gamma;
    const float2* b2 = (const float2*)beta;
    for (int n = tid; n < FFT_M; n += NTHREADS) {
        float2 v  = B[PIDX(n)];
        float2 g  = g2[n];
        float2 be = b2[n];
        orow[n] = make_float2(fmaf((v.x - mean) * inv, g.x, be.x),
                              fmaf((v.y - mean) * inv, g.y, be.y));
    }
}

extern "C" void kernel_launch(void* const* d_in, const int* in_sizes, int n_in,
                              void* d_out, int out_size) {
    const float* img   = (const float*)d_in[0];
    const float* txt   = (const float*)d_in[1];
    const int*   h1    = (const int*)  d_in[2];
    const int*   h2    = (const int*)  d_in[3];
    const float* s1    = (const float*)d_in[4];
    const float* s2    = (const float*)d_in[5];
    const float* gamma = (const float*)d_in[6];
    const float* beta  = (const float*)d_in[7];
    float* out = (float*)d_out;

    const int batch = in_sizes[0] / IMG_DIM;
    const size_t smem = 3 * PADDED * sizeof(float2);   // ~99 KB
    cudaFuncSetAttribute(bilinear_fusion_kernel,
                         cudaFuncAttributeMaxDynamicSharedMemorySize, (int)smem);
    bilinear_fusion_kernel<<<batch, NTHREADS, smem>>>(
        img, txt, h1, h2, s1, s2, gamma, beta, out);
}

// round 5
// speedup vs baseline: 1.3278x; 1.3278x over previous
#include <cuda_runtime.h>

#define FFT_M    4096   // complex FFT size (= d/2)
#define NREAL    8192   // sketch / output dim d
#define NTHREADS 512
#define IMG_DIM  2048
#define TXT_DIM  768

// Padded shared-memory indexing: one extra float2 every 32 float2 (256B)
// kills the 8/16-way bank conflicts of the strided Stockham writes.
#define PIDX(i)  ((i) + ((i) >> 5))            // float2 index -> padded float2 index
#define RIDX(i)  ((i) + (((i) >> 6) << 1))     // float  index -> padded float  index
#define PADDED   (FFT_M + (FFT_M >> 5))        // 4224 float2 per buffer

__device__ __forceinline__ float2 cadd(float2 a, float2 b){ return make_float2(a.x+b.x, a.y+b.y); }
__device__ __forceinline__ float2 csub(float2 a, float2 b){ return make_float2(a.x-b.x, a.y-b.y); }
__device__ __forceinline__ float2 cmul(float2 a, float2 b){
    return make_float2(fmaf(a.x, b.x, -a.y*b.y), fmaf(a.x, b.y, a.y*b.x));
}

// Radix-8 Stockham autosort FFT, size 4096, shared memory, padded layout.
// DIR = -1 forward, +1 inverse (unnormalized). 4 stages (even) => result back in x.
// 512 threads: exactly one radix-8 butterfly per thread per stage.
// Twiddle products interleaved with their uses to minimize register liveness.
// Ends with __syncthreads().
template<int DIR>
__device__ __forceinline__ void fft4096_r8(float2* __restrict__ x, float2* __restrict__ tmp, int tid) {
    const float c8 = 0.70710678118654752f;
    float2* in  = x;
    float2* out = tmp;
    #pragma unroll
    for (int stage = 0; stage < 4; stage++) {
        const int Ns   = 1 << (3 * stage);          // 1, 8, 64, 512
        const int m    = tid & (Ns - 1);
        const int base = ((tid - m) << 3) + m;

        float2 v0 = in[PIDX(tid)];
        float2 v1 = in[PIDX(tid +  512)];
        float2 v2 = in[PIDX(tid + 1024)];
        float2 v3 = in[PIDX(tid + 1536)];
        float2 v4 = in[PIDX(tid + 2048)];
        float2 v5 = in[PIDX(tid + 2560)];
        float2 v6 = in[PIDX(tid + 3072)];
        float2 v7 = in[PIDX(tid + 3584)];

        // twiddles W_{8Ns}^{r*m}, r=1..7 — interleaved product tree so that at
        // most three w-values are live at any point (register-pressure relief).
        {
            const float ang = (float)DIR * 6.2831853071795864f * (float)m / (8.0f * (float)Ns);
            float s, c; __sincosf(ang, &s, &c);
            float2 w1 = make_float2(c, s);
            v1 = cmul(v1, w1);
            float2 w2 = cmul(w1, w1);
            v2 = cmul(v2, w2);
            float2 w3 = cmul(w2, w1);
            v3 = cmul(v3, w3);
            float2 w4 = cmul(w2, w2);
            v4 = cmul(v4, w4);
            v5 = cmul(v5, cmul(w4, w1));
            v6 = cmul(v6, cmul(w4, w2));
            v7 = cmul(v7, cmul(w4, w3));
        }

        // 8-point FFT: even/odd 4-point FFTs + combine with constant W8^k
        float2 e0, e1, e2, e3, o0, o1, o2, o3;
        {
            float2 t0 = cadd(v0, v4), t1 = csub(v0, v4);
            float2 t2 = cadd(v2, v6), t3 = csub(v2, v6);
            float2 jt3 = (DIR < 0) ? make_float2(t3.y, -t3.x) : make_float2(-t3.y, t3.x);
            e0 = cadd(t0, t2); e2 = csub(t0, t2);
            e1 = cadd(t1, jt3); e3 = csub(t1, jt3);
        }
        {
            float2 t0 = cadd(v1, v5), t1 = csub(v1, v5);
            float2 t2 = cadd(v3, v7), t3 = csub(v3, v7);
            float2 jt3 = (DIR < 0) ? make_float2(t3.y, -t3.x) : make_float2(-t3.y, t3.x);
            o0 = cadd(t0, t2); o2 = csub(t0, t2);
            o1 = cadd(t1, jt3); o3 = csub(t1, jt3);
        }
        // u_k = W8^k * o_k (constants); store pairs immediately to retire regs
        out[PIDX(base         )] = cadd(e0, o0);
        out[PIDX(base + 4 * Ns)] = csub(e0, o0);
        float2 u1 = (DIR < 0) ? make_float2(c8*(o1.x + o1.y), c8*(o1.y - o1.x))
                              : make_float2(c8*(o1.x - o1.y), c8*(o1.x + o1.y));
        out[PIDX(base + 1 * Ns)] = cadd(e1, u1);
        out[PIDX(base + 5 * Ns)] = csub(e1, u1);
        float2 u2 = (DIR < 0) ? make_float2(o2.y, -o2.x)
                              : make_float2(-o2.y, o2.x);
        out[PIDX(base + 2 * Ns)] = cadd(e2, u2);
        out[PIDX(base + 6 * Ns)] = csub(e2, u2);
        float2 u3 = (DIR < 0) ? make_float2(c8*(o3.y - o3.x), -c8*(o3.x + o3.y))
                              : make_float2(-c8*(o3.x + o3.y), c8*(o3.x - o3.y));
        out[PIDX(base + 3 * Ns)] = cadd(e3, u3);
        out[PIDX(base + 7 * Ns)] = csub(e3, u3);

        __syncthreads();
        float2* sw = in; in = out; out = sw;
    }
}

__global__ void __launch_bounds__(NTHREADS, 2)
bilinear_fusion_kernel(
    const float* __restrict__ img,  const float* __restrict__ txt,
    const int*   __restrict__ h1,   const int*   __restrict__ h2,
    const float* __restrict__ s1,   const float* __restrict__ s2,
    const float* __restrict__ gamma,const float* __restrict__ beta,
    float* __restrict__ out)
{
    extern __shared__ float2 sm[];
    float2* A = sm;               // sketch1 -> Z1
    float2* B = sm +   PADDED;    // FFT scratch -> ZY -> y
    float2* C = sm + 2*PADDED;    // sketch2 -> Z2
    __shared__ float rs[16], rq[16];

    const int b   = blockIdx.x;
    const int tid = threadIdx.x;

    // ---- count sketches (scatter-add into smem) ----
    float* rA = (float*)A;
    float* rC = (float*)C;
    for (int i = tid; i < 2 * PADDED; i += NTHREADS) { rA[i] = 0.0f; rC[i] = 0.0f; }
    __syncthreads();

    const float* irow = img + (size_t)b * IMG_DIM;
    for (int i = tid; i < IMG_DIM; i += NTHREADS)
        atomicAdd(&rA[RIDX(h1[i])], irow[i] * s1[i]);
    const float* trow = txt + (size_t)b * TXT_DIM;
    for (int i = tid; i < TXT_DIM; i += NTHREADS)
        atomicAdd(&rC[RIDX(h2[i])], trow[i] * s2[i]);
    __syncthreads();

    // ---- forward FFTs of the packed real signals ----
    fft4096_r8<-1>(A, B, tid);   // Z1 in A
    fft4096_r8<-1>(C, B, tid);   // Z2 in C

    // ---- unpack rFFTs, multiply spectra, repack for inverse ----
    const float scale = 1.0f / (float)FFT_M;
    for (int k = tid; k <= FFT_M/2; k += NTHREADS) {
        int mk = (FFT_M - k) & (FFT_M - 1);
        float2 z1k = A[PIDX(k)],  z1m = A[PIDX(mk)];
        float2 z2k = C[PIDX(k)],  z2m = C[PIDX(mk)];
        float sa, ca;
        __sincosf(-6.2831853071795864f * (float)k / (float)NREAL, &sa, &ca);
        float2 w = make_float2(ca, sa);            // W_N^k

        float2 E1  = make_float2(0.5f*(z1k.x + z1m.x), 0.5f*(z1k.y - z1m.y));
        float2 O1t = make_float2(0.5f*(z1k.x - z1m.x), 0.5f*(z1k.y + z1m.y));
        float2 O1  = make_float2(O1t.y, -O1t.x);   // -i * O1t
        float2 WO1 = cmul(w, O1);
        float2 P1  = cadd(E1, WO1);
        float2 Q1  = csub(E1, WO1);

        float2 E2  = make_float2(0.5f*(z2k.x + z2m.x), 0.5f*(z2k.y - z2m.y));
        float2 O2t = make_float2(0.5f*(z2k.x - z2m.x), 0.5f*(z2k.y + z2m.y));
        float2 O2  = make_float2(O2t.y, -O2t.x);
        float2 WO2 = cmul(w, O2);
        float2 P2  = cadd(E2, WO2);
        float2 Q2  = csub(E2, WO2);

        float2 Yk  = cmul(P1, P2);
        float2 Ymc = cmul(Q1, Q2);                 // conj(Y[M-k])
        float2 G   = make_float2(0.5f*(Yk.x + Ymc.x), 0.5f*(Yk.y + Ymc.y));
        float2 Hm  = make_float2(0.5f*(Yk.x - Ymc.x), 0.5f*(Yk.y - Ymc.y));
        float2 H   = cmul(make_float2(w.x, -w.y), Hm);

        B[PIDX(k)] = make_float2(scale*(G.x - H.y), scale*(G.y + H.x));
        if (k != 0 && k != FFT_M/2) {
            B[PIDX(mk)] = make_float2(scale*(G.x + H.y), scale*(H.x - G.y));
        }
    }
    __syncthreads();

    // ---- inverse FFT: y[2n] = Re, y[2n+1] = Im ----
    fft4096_r8<1>(B, A, tid);

    // ---- LayerNorm over the 8192 reals ----
    float sum = 0.0f, sq = 0.0f;
    for (int n = tid; n < FFT_M; n += NTHREADS) {
        float2 v = B[PIDX(n)];
        sum += v.x + v.y;
        sq = fmaf(v.x, v.x, sq);
        sq = fmaf(v.y, v.y, sq);
    }
    #pragma unroll
    for (int o = 16; o; o >>= 1) {
        sum += __shfl_down_sync(0xffffffffu, sum, o);
        sq  += __shfl_down_sync(0xffffffffu, sq,  o);
    }
    const int wid = tid >> 5, lid = tid & 31;
    if (lid == 0) { rs[wid] = sum; rq[wid] = sq; }
    __syncthreads();
    if (wid == 0) {
        sum = (lid < 16) ? rs[lid] : 0.0f;
        sq  = (lid < 16) ? rq[lid] : 0.0f;
        #pragma unroll
        for (int o = 8; o; o >>= 1) {
            sum += __shfl_down_sync(0xffffffffu, sum, o);
            sq  += __shfl_down_sync(0xffffffffu, sq,  o);
        }
        if (lid == 0) { rs[0] = sum; rq[0] = sq; }
    }
    __syncthreads();
    const float mean = rs[0] * (1.0f / (float)NREAL);
    const float var  = rq[0] * (1.0f / (float)NREAL) - mean * mean;
    const float inv  = rsqrtf(var + 1e-5f);

    float2* orow = (float2*)(out + (size_t)b * NREAL);
    const float2* g2 = (const float2*)gamma;
    const float2* b2 = (const float2*)beta;
    for (int n = tid; n < FFT_M; n += NTHREADS) {
        float2 v  = B[PIDX(n)];
        float2 g  = g2[n];
        float2 be = b2[n];
        orow[n] = make_float2(fmaf((v.x - mean) * inv, g.x, be.x),
                              fmaf((v.y - mean) * inv, g.y, be.y));
    }
}

extern "C" void kernel_launch(void* const* d_in, const int* in_sizes, int n_in,
                              void* d_out, int out_size) {
    const float* img   = (const float*)d_in[0];
    const float* txt   = (const float*)d_in[1];
    const int*   h1    = (const int*)  d_in[2];
    const int*   h2    = (const int*)  d_in[3];
    const float* s1    = (const float*)d_in[4];
    const float* s2    = (const float*)d_in[5];
    const float* gamma = (const float*)d_in[6];
    const float* beta  = (const float*)d_in[7];
    float* out = (float*)d_out;

    const int batch = in_sizes[0] / IMG_DIM;
    const size_t smem = 3 * PADDED * sizeof(float2);   // ~99 KB
    cudaFuncSetAttribute(bilinear_fusion_kernel,
                         cudaFuncAttributeMaxDynamicSharedMemorySize, (int)smem);
    bilinear_fusion_kernel<<<batch, NTHREADS, smem>>>(
        img, txt, h1, h2, s1, s2, gamma, beta, out);
}